// round 7
// baseline (speedup 1.0000x reference)
#include <cuda_runtime.h>
#include <cuda_bf16.h>
#include <mma.h>
#include <cstdint>
#include <cfloat>

using namespace nvcuda;

// Problem constants
#define B_    64
#define P_    56
#define N_    3136      // P*P
#define DIM_  256
#define HEADS_ 4
#define HD_   24
#define M_    16
#define OUT_  256
#define BH_   256       // B*HEADS

// ---------------- scratch (no allocation; __device__ globals) ----------------
__device__ float g_f[(size_t)BH_ * N_ * HD_];
__device__ float g_v[(size_t)BH_ * N_ * HD_];
__device__ float g_centers_n[BH_ * M_ * HD_];       // EXACT normalized centers
__device__ float g_value_centers[BH_ * M_ * HD_];   // EXACT value centers
__device__ float g_agg[BH_ * M_ * HD_];
__device__ int   g_assign[(size_t)BH_ * N_];
__device__ float g_sval[(size_t)BH_ * N_];
// pre-split weights (hi/lo bf16)
__device__ __nv_bfloat16 g_wh[192 * 256], g_wl[192 * 256];   // [col][d], col<96 f_w else v_w
__device__ __nv_bfloat16 g_ph[256 * 96],  g_pl[256 * 96];    // proj_w

typedef wmma::fragment<wmma::matrix_a, 16, 16, 16, __nv_bfloat16, wmma::row_major> FragA;
typedef wmma::fragment<wmma::matrix_b, 16, 16, 16, __nv_bfloat16, wmma::col_major> FragB;
typedef wmma::fragment<wmma::accumulator, 16, 16, 16, float> FragC;

__device__ __forceinline__ void bsplit(float v, __nv_bfloat16& h, __nv_bfloat16& l) {
    h = __float2bfloat16(v);
    l = __float2bfloat16(v - __bfloat162float(h));
}
__device__ __forceinline__ uint32_t packbf(__nv_bfloat16 a, __nv_bfloat16 b) {
    return (uint32_t)__bfloat16_as_ushort(a) | ((uint32_t)__bfloat16_as_ushort(b) << 16);
}

// =====================================================================
// K0: split weights to bf16 hi/lo once.
// =====================================================================
__global__ __launch_bounds__(256) void k_split_w(
    const float* __restrict__ f_w, const float* __restrict__ v_w,
    const float* __restrict__ proj_w)
{
    int i = blockIdx.x * 256 + threadIdx.x;    // 0 .. 49151
    {
        int col = i >> 8, d = i & 255;
        float v = (col < 96) ? f_w[col * 256 + d] : v_w[(col - 96) * 256 + d];
        __nv_bfloat16 h, l; bsplit(v, h, l);
        g_wh[i] = h; g_wl[i] = l;
    }
    if (i < 256 * 96) {
        __nv_bfloat16 h, l; bsplit(proj_w[i], h, l);
        g_ph[i] = h; g_pl[i] = l;
    }
}

// =====================================================================
// K1: fused feat/val GEMM. Block 64 rows x 192 cols (full width), 128 thr,
// 4 warps each 64x48. K-chunk 32. x read ONCE; weights pre-split.
// =====================================================================
#define G1_LD 40   // 32 + 8
__global__ __launch_bounds__(128) void k_gemm_fv_mma(
    const float* __restrict__ x,
    const float* __restrict__ f_b, const float* __restrict__ v_b)
{
    __shared__ __align__(32) unsigned char pool[40960];
    __nv_bfloat16* Ah = (__nv_bfloat16*)pool;            // 64*40
    __nv_bfloat16* Al = Ah + 64 * G1_LD;
    __nv_bfloat16* Bh = Al + 64 * G1_LD;                 // 192*40
    __nv_bfloat16* Bl = Bh + 192 * G1_LD;
    float* stage = (float*)pool;                         // 64 x 100 (pass-wise)

    const int tid = threadIdx.x;
    const int wid = tid >> 5;
    const int r0 = blockIdx.x * 64;
    const int bb = r0 / N_;           // 3136 % 64 == 0 -> uniform
    const int n0 = r0 - bb * N_;

    FragC acc[4][3];
#pragma unroll
    for (int mi = 0; mi < 4; mi++)
#pragma unroll
        for (int ni = 0; ni < 3; ni++) wmma::fill_fragment(acc[mi][ni], 0.f);

    for (int kc = 0; kc < DIM_; kc += 32) {
        // X tile [64 x 32] fp32 -> split, packed uint2 stores
#pragma unroll
        for (int s = tid; s < 512; s += 128) {
            int row = s >> 3, q = (s & 7) * 4;
            float4 v = *(const float4*)(x + (size_t)(r0 + row) * DIM_ + kc + q);
            __nv_bfloat16 h0, h1, h2, h3, l0, l1, l2, l3;
            bsplit(v.x, h0, l0); bsplit(v.y, h1, l1);
            bsplit(v.z, h2, l2); bsplit(v.w, h3, l3);
            uint2 uh = make_uint2(packbf(h0, h1), packbf(h2, h3));
            uint2 ul = make_uint2(packbf(l0, l1), packbf(l2, l3));
            *(uint2*)(Ah + row * G1_LD + q) = uh;
            *(uint2*)(Al + row * G1_LD + q) = ul;
        }
        // W tile [192 x 32] bf16 pre-split: 768 uint4 per array
#pragma unroll
        for (int s = tid; s < 768; s += 128) {
            int row = s >> 2, q = (s & 3) * 8;
            *(uint4*)(Bh + row * G1_LD + q) = *(const uint4*)(g_wh + (size_t)row * DIM_ + kc + q);
            *(uint4*)(Bl + row * G1_LD + q) = *(const uint4*)(g_wl + (size_t)row * DIM_ + kc + q);
        }
        __syncthreads();

#pragma unroll
        for (int ks = 0; ks < 32; ks += 16) {
            FragA ah[4], al[4];
#pragma unroll
            for (int mi = 0; mi < 4; mi++) {
                wmma::load_matrix_sync(ah[mi], Ah + (mi * 16) * G1_LD + ks, G1_LD);
                wmma::load_matrix_sync(al[mi], Al + (mi * 16) * G1_LD + ks, G1_LD);
            }
#pragma unroll
            for (int ni = 0; ni < 3; ni++) {
                FragB bh, bl;
                int cb = (wid * 48 + ni * 16) * G1_LD + ks;
                wmma::load_matrix_sync(bh, Bh + cb, G1_LD);
                wmma::load_matrix_sync(bl, Bl + cb, G1_LD);
#pragma unroll
                for (int mi = 0; mi < 4; mi++) {
                    wmma::mma_sync(acc[mi][ni], ah[mi], bh, acc[mi][ni]);
                    wmma::mma_sync(acc[mi][ni], ah[mi], bl, acc[mi][ni]);
                    wmma::mma_sync(acc[mi][ni], al[mi], bh, acc[mi][ni]);
                }
            }
        }
        __syncthreads();
    }

    // epilogue: two passes of 96 cols (pass 0 -> g_f, pass 1 -> g_v)
    for (int p = 0; p < 2; p++) {
        if ((wid >> 1) == p) {
            int wl = wid & 1;
#pragma unroll
            for (int mi = 0; mi < 4; mi++)
#pragma unroll
                for (int ni = 0; ni < 3; ni++)
                    wmma::store_matrix_sync(stage + (size_t)(mi * 16) * 100
                                                  + wl * 48 + ni * 16,
                                            acc[mi][ni], 100, wmma::mem_row_major);
        }
        __syncthreads();
#pragma unroll
        for (int s = tid; s < 6144; s += 128) {
            int row = s / 96, lc = s % 96;
            float val = stage[row * 100 + lc];
            int e = lc / HD_, hd = lc % HD_;
            int n = n0 + row;
            if (p == 0)
                g_f[((size_t)(bb * HEADS_ + e) * N_ + n) * HD_ + hd] = val + f_b[lc];
            else
                g_v[((size_t)(bb * HEADS_ + e) * N_ + n) * HD_ + hd] = val + v_b[lc];
        }
        __syncthreads();
    }
}

// =====================================================================
// K2: EXACT centers via linearity (unchanged from round 6).
// =====================================================================
__global__ __launch_bounds__(256) void k_centers(
    const float* __restrict__ x,
    const float* __restrict__ f_w, const float* __restrict__ f_b,
    const float* __restrict__ v_w, const float* __restrict__ v_b)
{
    __shared__ float px[256];
    __shared__ float cf[192];
    __shared__ float ninv[4];

    const int g = blockIdx.x;
    const int b = g >> 4;
    const int m = g & 15;
    const int pw = m >> 2, ph = m & 3;
    const int tid = threadIdx.x;
    const int wid = tid >> 5, lane = tid & 31;

    {
        float s = 0.f;
        const float* xb = x + (size_t)b * N_ * DIM_ + tid;
#pragma unroll 4
        for (int it = 0; it < 196; it++) {
            int dw = it / 14, dh = it % 14;
            int n = (pw * 14 + dw) * P_ + ph * 14 + dh;
            s += xb[(size_t)n * DIM_];
        }
        px[tid] = s * (1.f / 196.f);
    }
    __syncthreads();

    for (int c = 0; c < 24; c++) {
        int col = wid + c * 8;
        const float* wr = (col < 96) ? (f_w + (size_t)col * DIM_)
                                     : (v_w + (size_t)(col - 96) * DIM_);
        float p = 0.f;
#pragma unroll
        for (int j = 0; j < 8; j++)
            p = fmaf(px[lane + j * 32], wr[lane + j * 32], p);
#pragma unroll
        for (int off = 16; off > 0; off >>= 1)
            p += __shfl_xor_sync(0xffffffffu, p, off);
        if (lane == 0)
            cf[col] = p + ((col < 96) ? f_b[col] : v_b[col - 96]);
    }
    __syncthreads();

    if (tid < 4) {
        float ss = 0.f;
#pragma unroll
        for (int k = 0; k < 24; k++) { float t = cf[tid * 24 + k]; ss += t * t; }
        ninv[tid] = 1.f / fmaxf(sqrtf(ss), 1e-12f);
    }
    __syncthreads();

    if (tid < 96) {
        int e = tid / 24, k = tid % 24;
        g_centers_n[((b * HEADS_ + e) * M_ + m) * HD_ + k] = cf[tid] * ninv[e];
    } else if (tid < 192) {
        int c2 = tid - 96;
        int e = c2 / 24, k = c2 % 24;
        g_value_centers[((b * HEADS_ + e) * M_ + m) * HD_ + k] = cf[tid];
    }
}

// =====================================================================
// K3: per-bh clustering with fp32 refinement (unchanged from round 6).
// =====================================================================
__global__ __launch_bounds__(512) void k_cluster(
    const float* __restrict__ x,
    const float* __restrict__ f_w, const float* __restrict__ f_b,
    const float* __restrict__ sim_alpha, const float* __restrict__ sim_beta)
{
    __shared__ float cn[M_ * HD_];
    __shared__ unsigned char assign_sh[N_];
    __shared__ unsigned char flag_sh[N_];
    __shared__ float sval_sh[N_];

    const int bh  = blockIdx.x;
    const int b   = bh / HEADS_;
    const int e   = bh % HEADS_;
    const int tid = threadIdx.x;
    const int wid = tid >> 5, lane = tid & 31;
    const float alpha = sim_alpha[0];
    const float beta  = sim_beta[0];
    const float Tflag = fabsf(alpha) * 1e-3f + 1e-7f;

    for (int l = tid; l < M_ * HD_; l += 512)
        cn[l] = g_centers_n[bh * M_ * HD_ + l];
    __syncthreads();

    for (int n = tid; n < N_; n += 512) {
        float fv[24];
        const float4* fp4 = (const float4*)(g_f + ((size_t)bh * N_ + n) * HD_);
#pragma unroll
        for (int q = 0; q < 6; q++) {
            float4 t = fp4[q];
            fv[q * 4 + 0] = t.x; fv[q * 4 + 1] = t.y;
            fv[q * 4 + 2] = t.z; fv[q * 4 + 3] = t.w;
        }
        float ss = 0.f;
#pragma unroll
        for (int k = 0; k < 24; k++) ss += fv[k] * fv[k];
        float inv = 1.f / fmaxf(sqrtf(ss), 1e-12f);

        float best = -FLT_MAX, second = -FLT_MAX;
        int bi = 0;
#pragma unroll
        for (int m = 0; m < M_; m++) {
            float d = 0.f;
#pragma unroll
            for (int k = 0; k < 24; k++) d = fmaf(cn[m * HD_ + k], fv[k], d);
            float t = beta + alpha * (d * inv);
            t = (t >= 0.f) ? t : 0.2f * t;
            if (t > best) { second = best; best = t; bi = m; }
            else if (t > second) second = t;
        }
        assign_sh[n] = (unsigned char)bi;
        sval_sh[n]   = best;
        flag_sh[n]   = (best - second <= Tflag) ? 1 : 0;
        g_assign[(size_t)bh * N_ + n] = bi;
        g_sval[(size_t)bh * N_ + n]   = best;
    }
    __syncthreads();

    {
        const int nb = wid * 196;
        for (int n = nb; n < nb + 196; n++) {
            if (!flag_sh[n]) continue;
            const float* xr = x + ((size_t)b * N_ + n) * DIM_;
            float xr8[8];
#pragma unroll
            for (int j = 0; j < 8; j++) xr8[j] = xr[lane + j * 32];
            float fex[24];
#pragma unroll
            for (int k = 0; k < 24; k++) {
                const float* wr = f_w + (size_t)(e * 24 + k) * DIM_;
                float p = 0.f;
#pragma unroll
                for (int j = 0; j < 8; j++)
                    p = fmaf(xr8[j], wr[lane + j * 32], p);
#pragma unroll
                for (int off = 16; off > 0; off >>= 1)
                    p += __shfl_xor_sync(0xffffffffu, p, off);
                fex[k] = p + f_b[e * 24 + k];
            }
            float ss = 0.f;
#pragma unroll
            for (int k = 0; k < 24; k++) ss += fex[k] * fex[k];
            float inv = 1.f / fmaxf(sqrtf(ss), 1e-12f);

            float t = -FLT_MAX;
            int idx = 1000;
            if (lane < M_) {
                float d = 0.f;
#pragma unroll
                for (int k = 0; k < 24; k++) d = fmaf(cn[lane * HD_ + k], fex[k], d);
                t = beta + alpha * (d * inv);
                t = (t >= 0.f) ? t : 0.2f * t;
                idx = lane;
            }
#pragma unroll
            for (int off = 16; off > 0; off >>= 1) {
                float ot = __shfl_xor_sync(0xffffffffu, t, off);
                int   oi = __shfl_xor_sync(0xffffffffu, idx, off);
                if (ot > t || (ot == t && oi < idx)) { t = ot; idx = oi; }
            }
            if (lane == 0) {
                assign_sh[n] = (unsigned char)idx;
                sval_sh[n]   = t;
                g_assign[(size_t)bh * N_ + n] = idx;
                g_sval[(size_t)bh * N_ + n]   = t;
            }
        }
    }
    __syncthreads();

    const int w = wid;
    float acc[24];
#pragma unroll
    for (int k = 0; k < 24; k++) acc[k] = 0.f;
    int cnt = 0;

    for (int n = lane; n < N_; n += 32) {
        if (assign_sh[n] == (unsigned char)w) {
            float s = sval_sh[n];
            const float4* vp4 = (const float4*)(g_v + ((size_t)bh * N_ + n) * HD_);
#pragma unroll
            for (int q = 0; q < 6; q++) {
                float4 t = vp4[q];
                acc[q * 4 + 0] = fmaf(s, t.x, acc[q * 4 + 0]);
                acc[q * 4 + 1] = fmaf(s, t.y, acc[q * 4 + 1]);
                acc[q * 4 + 2] = fmaf(s, t.z, acc[q * 4 + 2]);
                acc[q * 4 + 3] = fmaf(s, t.w, acc[q * 4 + 3]);
            }
            cnt++;
        }
    }
#pragma unroll
    for (int off = 16; off > 0; off >>= 1) {
#pragma unroll
        for (int k = 0; k < 24; k++)
            acc[k] += __shfl_xor_sync(0xffffffffu, acc[k], off);
        cnt += __shfl_xor_sync(0xffffffffu, cnt, off);
    }
    if (lane == 0) {
        float denom = 1.f / ((float)cnt + 1.f);
        const float* vc = g_value_centers + (bh * M_ + w) * HD_;
        float* dst = g_agg + (bh * M_ + w) * HD_;
#pragma unroll
        for (int k = 0; k < 24; k++)
            dst[k] = (acc[k] + vc[k]) * denom;
    }
}

// =====================================================================
// K4: dispatch + projection. Block 64 tokens x 128 cols (grid.y=2),
// 128 thr, 4 warps 2x2 (warp 32x64). A resident K=96; B staged per
// 32-chunk from pre-split proj.
// =====================================================================
#define O_LDA 104   // 96 + 8
#define O_LDB 40    // 32 + 8
__global__ __launch_bounds__(128) void k_out_mma(
    const float* __restrict__ proj_b, float* __restrict__ out)
{
    __shared__ __align__(32) unsigned char pool[47104];
    __nv_bfloat16* Ah = (__nv_bfloat16*)pool;          // 64*104
    __nv_bfloat16* Al = Ah + 64 * O_LDA;
    __nv_bfloat16* Bh = Al + 64 * O_LDA;               // 128*40
    __nv_bfloat16* Bl = Bh + 128 * O_LDB;
    float* stage = (float*)pool;                       // 64 x 132

    const int tid = threadIdx.x;
    const int wid = tid >> 5;
    const int wm = wid & 1;
    const int wn = wid >> 1;
    const int r0 = blockIdx.x * 64;
    const int c0 = blockIdx.y * 128;
    const int bb = r0 / N_;          // uniform
    const int n0 = r0 - bb * N_;

    // build merged A (hi/lo), packed uint32 stores
    for (int idx = tid; idx < 256; idx += 128) {
        int trow = idx >> 2, e = idx & 3;
        int n = n0 + trow;
        size_t aix = (size_t)(bb * HEADS_ + e) * N_ + n;
        int   c = g_assign[aix];
        float s = g_sval[aix];
        const float* ag = g_agg + ((size_t)(bb * HEADS_ + e) * M_ + c) * HD_;
        uint32_t* ah = (uint32_t*)(Ah + trow * O_LDA + e * HD_);
        uint32_t* al = (uint32_t*)(Al + trow * O_LDA + e * HD_);
#pragma unroll
        for (int k2 = 0; k2 < 12; k2++) {
            __nv_bfloat16 h0, l0, h1, l1;
            bsplit(s * ag[2 * k2],     h0, l0);
            bsplit(s * ag[2 * k2 + 1], h1, l1);
            ah[k2] = packbf(h0, h1);
            al[k2] = packbf(l0, l1);
        }
    }

    FragC acc[2][4];
#pragma unroll
    for (int mi = 0; mi < 2; mi++)
#pragma unroll
        for (int ni = 0; ni < 4; ni++) wmma::fill_fragment(acc[mi][ni], 0.f);

    for (int ch = 0; ch < 3; ch++) {
        const int kc = ch * 32;
        __syncthreads();   // A build done (ch0) / prior B reads done (ch>0)
#pragma unroll
        for (int s = tid; s < 512; s += 128) {
            int row = s >> 2, q = (s & 3) * 8;
            *(uint4*)(Bh + row * O_LDB + q) =
                *(const uint4*)(g_ph + (size_t)(c0 + row) * 96 + kc + q);
            *(uint4*)(Bl + row * O_LDB + q) =
                *(const uint4*)(g_pl + (size_t)(c0 + row) * 96 + kc + q);
        }
        __syncthreads();

#pragma unroll
        for (int ks = 0; ks < 32; ks += 16) {
            FragA ah2[2], al2[2];
#pragma unroll
            for (int mi = 0; mi < 2; mi++) {
                int rb = (wm * 32 + mi * 16) * O_LDA + kc + ks;
                wmma::load_matrix_sync(ah2[mi], Ah + rb, O_LDA);
                wmma::load_matrix_sync(al2[mi], Al + rb, O_LDA);
            }
#pragma unroll
            for (int ni = 0; ni < 4; ni++) {
                FragB bh, bl;
                int cb = (wn * 64 + ni * 16) * O_LDB + ks;
                wmma::load_matrix_sync(bh, Bh + cb, O_LDB);
                wmma::load_matrix_sync(bl, Bl + cb, O_LDB);
#pragma unroll
                for (int mi = 0; mi < 2; mi++) {
                    wmma::mma_sync(acc[mi][ni], ah2[mi], bh, acc[mi][ni]);
                    wmma::mma_sync(acc[mi][ni], ah2[mi], bl, acc[mi][ni]);
                    wmma::mma_sync(acc[mi][ni], al2[mi], bh, acc[mi][ni]);
                }
            }
        }
    }
    __syncthreads();

#pragma unroll
    for (int mi = 0; mi < 2; mi++)
#pragma unroll
        for (int ni = 0; ni < 4; ni++)
            wmma::store_matrix_sync(stage + (size_t)(wm * 32 + mi * 16) * 132
                                          + wn * 64 + ni * 16,
                                    acc[mi][ni], 132, wmma::mem_row_major);
    __syncthreads();

#pragma unroll
    for (int s = tid; s < 2048; s += 128) {
        int row = s >> 5, c4 = (s & 31) * 4;
        float4 v = *(float4*)(stage + row * 132 + c4);
        float4 b = *(const float4*)(proj_b + c0 + c4);
        v.x += b.x; v.y += b.y; v.z += b.z; v.w += b.w;
        *(float4*)(out + (size_t)(r0 + row) * OUT_ + c0 + c4) = v;
    }
}

// =====================================================================
extern "C" void kernel_launch(void* const* d_in, const int* in_sizes, int n_in,
                              void* d_out, int out_size)
{
    (void)in_sizes; (void)n_in; (void)out_size;
    const float* x         = (const float*)d_in[0];
    const float* f_w       = (const float*)d_in[1];
    const float* f_b       = (const float*)d_in[2];
    const float* v_w       = (const float*)d_in[3];
    const float* v_b       = (const float*)d_in[4];
    const float* proj_w    = (const float*)d_in[5];
    const float* proj_b    = (const float*)d_in[6];
    const float* sim_alpha = (const float*)d_in[7];
    const float* sim_beta  = (const float*)d_in[8];
    float* out = (float*)d_out;

    k_split_w<<<192, 256>>>(f_w, v_w, proj_w);
    k_gemm_fv_mma<<<(B_ * N_) / 64, 128>>>(x, f_b, v_b);
    k_centers<<<B_ * M_, 256>>>(x, f_w, f_b, v_w, v_b);
    k_cluster<<<BH_, 512>>>(x, f_w, f_b, sim_alpha, sim_beta);
    dim3 g2((B_ * N_) / 64, 2);
    k_out_mma<<<g2, 128>>>(proj_b, out);
}

// round 8
// speedup vs baseline: 1.3212x; 1.3212x over previous
#include <cuda_runtime.h>
#include <cuda_bf16.h>
#include <mma.h>
#include <cstdint>
#include <cfloat>

using namespace nvcuda;

// Problem constants
#define B_    64
#define P_    56
#define N_    3136      // P*P
#define DIM_  256
#define HEADS_ 4
#define HD_   24
#define M_    16
#define OUT_  256
#define BH_   256       // B*HEADS

// ---------------- scratch (no allocation; __device__ globals) ----------------
__device__ float g_f[(size_t)BH_ * N_ * HD_];
__device__ float g_v[(size_t)BH_ * N_ * HD_];
__device__ float g_centers_n[BH_ * M_ * HD_];       // EXACT normalized centers
__device__ float g_value_centers[BH_ * M_ * HD_];   // EXACT value centers
__device__ float g_agg[BH_ * M_ * HD_];
__device__ unsigned char g_assign8[(size_t)BH_ * N_];
__device__ float g_sval[(size_t)BH_ * N_];
// pre-split weights (hi/lo bf16)
__device__ __nv_bfloat16 g_wh[192 * 256], g_wl[192 * 256];   // [col][d]
__device__ __nv_bfloat16 g_ph[256 * 96],  g_pl[256 * 96];    // proj_w

typedef wmma::fragment<wmma::matrix_a, 16, 16, 16, __nv_bfloat16, wmma::row_major> FragA;
typedef wmma::fragment<wmma::matrix_b, 16, 16, 16, __nv_bfloat16, wmma::col_major> FragB;
typedef wmma::fragment<wmma::accumulator, 16, 16, 16, float> FragC;

__device__ __forceinline__ void bsplit(float v, __nv_bfloat16& h, __nv_bfloat16& l) {
    h = __float2bfloat16(v);
    l = __float2bfloat16(v - __bfloat162float(h));
}
__device__ __forceinline__ uint32_t packbf(__nv_bfloat16 a, __nv_bfloat16 b) {
    return (uint32_t)__bfloat16_as_ushort(a) | ((uint32_t)__bfloat16_as_ushort(b) << 16);
}

// =====================================================================
// K0: split weights to bf16 hi/lo once.
// =====================================================================
__global__ __launch_bounds__(256) void k_split_w(
    const float* __restrict__ f_w, const float* __restrict__ v_w,
    const float* __restrict__ proj_w)
{
    int i = blockIdx.x * 256 + threadIdx.x;    // 0 .. 49151
    {
        int col = i >> 8, d = i & 255;
        float v = (col < 96) ? f_w[col * 256 + d] : v_w[(col - 96) * 256 + d];
        __nv_bfloat16 h, l; bsplit(v, h, l);
        g_wh[i] = h; g_wl[i] = l;
    }
    if (i < 256 * 96) {
        __nv_bfloat16 h, l; bsplit(proj_w[i], h, l);
        g_ph[i] = h; g_pl[i] = l;
    }
}

// =====================================================================
// K1: fused feat/val GEMM (round-7, unchanged).
// =====================================================================
#define G1_LD 40   // 32 + 8
__global__ __launch_bounds__(128) void k_gemm_fv_mma(
    const float* __restrict__ x,
    const float* __restrict__ f_b, const float* __restrict__ v_b)
{
    __shared__ __align__(32) unsigned char pool[40960];
    __nv_bfloat16* Ah = (__nv_bfloat16*)pool;            // 64*40
    __nv_bfloat16* Al = Ah + 64 * G1_LD;
    __nv_bfloat16* Bh = Al + 64 * G1_LD;                 // 192*40
    __nv_bfloat16* Bl = Bh + 192 * G1_LD;
    float* stage = (float*)pool;                         // 64 x 100

    const int tid = threadIdx.x;
    const int wid = tid >> 5;
    const int r0 = blockIdx.x * 64;
    const int bb = r0 / N_;
    const int n0 = r0 - bb * N_;

    FragC acc[4][3];
#pragma unroll
    for (int mi = 0; mi < 4; mi++)
#pragma unroll
        for (int ni = 0; ni < 3; ni++) wmma::fill_fragment(acc[mi][ni], 0.f);

    for (int kc = 0; kc < DIM_; kc += 32) {
#pragma unroll
        for (int s = tid; s < 512; s += 128) {
            int row = s >> 3, q = (s & 7) * 4;
            float4 v = *(const float4*)(x + (size_t)(r0 + row) * DIM_ + kc + q);
            __nv_bfloat16 h0, h1, h2, h3, l0, l1, l2, l3;
            bsplit(v.x, h0, l0); bsplit(v.y, h1, l1);
            bsplit(v.z, h2, l2); bsplit(v.w, h3, l3);
            *(uint2*)(Ah + row * G1_LD + q) = make_uint2(packbf(h0, h1), packbf(h2, h3));
            *(uint2*)(Al + row * G1_LD + q) = make_uint2(packbf(l0, l1), packbf(l2, l3));
        }
#pragma unroll
        for (int s = tid; s < 768; s += 128) {
            int row = s >> 2, q = (s & 3) * 8;
            *(uint4*)(Bh + row * G1_LD + q) = *(const uint4*)(g_wh + (size_t)row * DIM_ + kc + q);
            *(uint4*)(Bl + row * G1_LD + q) = *(const uint4*)(g_wl + (size_t)row * DIM_ + kc + q);
        }
        __syncthreads();

#pragma unroll
        for (int ks = 0; ks < 32; ks += 16) {
            FragA ah[4], al[4];
#pragma unroll
            for (int mi = 0; mi < 4; mi++) {
                wmma::load_matrix_sync(ah[mi], Ah + (mi * 16) * G1_LD + ks, G1_LD);
                wmma::load_matrix_sync(al[mi], Al + (mi * 16) * G1_LD + ks, G1_LD);
            }
#pragma unroll
            for (int ni = 0; ni < 3; ni++) {
                FragB bh, bl;
                int cb = (wid * 48 + ni * 16) * G1_LD + ks;
                wmma::load_matrix_sync(bh, Bh + cb, G1_LD);
                wmma::load_matrix_sync(bl, Bl + cb, G1_LD);
#pragma unroll
                for (int mi = 0; mi < 4; mi++) {
                    wmma::mma_sync(acc[mi][ni], ah[mi], bh, acc[mi][ni]);
                    wmma::mma_sync(acc[mi][ni], ah[mi], bl, acc[mi][ni]);
                    wmma::mma_sync(acc[mi][ni], al[mi], bh, acc[mi][ni]);
                }
            }
        }
        __syncthreads();
    }

    for (int p = 0; p < 2; p++) {
        if ((wid >> 1) == p) {
            int wl = wid & 1;
#pragma unroll
            for (int mi = 0; mi < 4; mi++)
#pragma unroll
                for (int ni = 0; ni < 3; ni++)
                    wmma::store_matrix_sync(stage + (size_t)(mi * 16) * 100
                                                  + wl * 48 + ni * 16,
                                            acc[mi][ni], 100, wmma::mem_row_major);
        }
        __syncthreads();
#pragma unroll
        for (int s = tid; s < 6144; s += 128) {
            int row = s / 96, lc = s % 96;
            float val = stage[row * 100 + lc];
            int e = lc / HD_, hd = lc % HD_;
            int n = n0 + row;
            if (p == 0)
                g_f[((size_t)(bb * HEADS_ + e) * N_ + n) * HD_ + hd] = val + f_b[lc];
            else
                g_v[((size_t)(bb * HEADS_ + e) * N_ + n) * HD_ + hd] = val + v_b[lc];
        }
        __syncthreads();
    }
}

// =====================================================================
// K2: EXACT centers via linearity (unchanged).
// =====================================================================
__global__ __launch_bounds__(256) void k_centers(
    const float* __restrict__ x,
    const float* __restrict__ f_w, const float* __restrict__ f_b,
    const float* __restrict__ v_w, const float* __restrict__ v_b)
{
    __shared__ float px[256];
    __shared__ float cf[192];
    __shared__ float ninv[4];

    const int g = blockIdx.x;
    const int b = g >> 4;
    const int m = g & 15;
    const int pw = m >> 2, ph = m & 3;
    const int tid = threadIdx.x;
    const int wid = tid >> 5, lane = tid & 31;

    {
        float s = 0.f;
        const float* xb = x + (size_t)b * N_ * DIM_ + tid;
#pragma unroll 4
        for (int it = 0; it < 196; it++) {
            int dw = it / 14, dh = it % 14;
            int n = (pw * 14 + dw) * P_ + ph * 14 + dh;
            s += xb[(size_t)n * DIM_];
        }
        px[tid] = s * (1.f / 196.f);
    }
    __syncthreads();

    for (int c = 0; c < 24; c++) {
        int col = wid + c * 8;
        const float* wr = (col < 96) ? (f_w + (size_t)col * DIM_)
                                     : (v_w + (size_t)(col - 96) * DIM_);
        float p = 0.f;
#pragma unroll
        for (int j = 0; j < 8; j++)
            p = fmaf(px[lane + j * 32], wr[lane + j * 32], p);
#pragma unroll
        for (int off = 16; off > 0; off >>= 1)
            p += __shfl_xor_sync(0xffffffffu, p, off);
        if (lane == 0)
            cf[col] = p + ((col < 96) ? f_b[col] : v_b[col - 96]);
    }
    __syncthreads();

    if (tid < 4) {
        float ss = 0.f;
#pragma unroll
        for (int k = 0; k < 24; k++) { float t = cf[tid * 24 + k]; ss += t * t; }
        ninv[tid] = 1.f / fmaxf(sqrtf(ss), 1e-12f);
    }
    __syncthreads();

    if (tid < 96) {
        int e = tid / 24, k = tid % 24;
        g_centers_n[((b * HEADS_ + e) * M_ + m) * HD_ + k] = cf[tid] * ninv[e];
    } else if (tid < 192) {
        int c2 = tid - 96;
        int e = c2 / 24, k = c2 % 24;
        g_value_centers[((b * HEADS_ + e) * M_ + m) * HD_ + k] = cf[tid];
    }
}

// =====================================================================
// K3a: assignment. grid = BH_*8 (2048 blocks), 256 thr; 392 tokens/block.
// Per-token sims from bf16-split g_f + warp-local fp32 refinement of
// near-ties via ballot (identical numerics to round-6 refinement).
// =====================================================================
__global__ __launch_bounds__(256) void k_assign(
    const float* __restrict__ x,
    const float* __restrict__ f_w, const float* __restrict__ f_b,
    const float* __restrict__ sim_alpha, const float* __restrict__ sim_beta)
{
    __shared__ float cn[M_ * HD_];

    const int bh  = blockIdx.x >> 3;
    const int tile = blockIdx.x & 7;
    const int t0  = tile * 392;
    const int b   = bh / HEADS_;
    const int e   = bh % HEADS_;
    const int tid = threadIdx.x;
    const int lane = tid & 31;
    const float alpha = sim_alpha[0];
    const float beta  = sim_beta[0];
    const float Tflag = fabsf(alpha) * 1e-3f + 1e-7f;

    for (int l = tid; l < M_ * HD_; l += 256)
        cn[l] = g_centers_n[bh * M_ * HD_ + l];
    __syncthreads();

    for (int pass = 0; pass < 2; pass++) {
        const int n = t0 + pass * 256 + tid;
        const bool valid = (pass * 256 + tid) < 392;
        int bi = 0;
        float best = -FLT_MAX;
        bool flag = false;

        if (valid) {
            float fv[24];
            const float4* fp4 = (const float4*)(g_f + ((size_t)bh * N_ + n) * HD_);
#pragma unroll
            for (int q = 0; q < 6; q++) {
                float4 t = fp4[q];
                fv[q * 4 + 0] = t.x; fv[q * 4 + 1] = t.y;
                fv[q * 4 + 2] = t.z; fv[q * 4 + 3] = t.w;
            }
            float ss = 0.f;
#pragma unroll
            for (int k = 0; k < 24; k++) ss += fv[k] * fv[k];
            float inv = 1.f / fmaxf(sqrtf(ss), 1e-12f);

            float second = -FLT_MAX;
#pragma unroll
            for (int m = 0; m < M_; m++) {
                float d = 0.f;
#pragma unroll
                for (int k = 0; k < 24; k++) d = fmaf(cn[m * HD_ + k], fv[k], d);
                float t = beta + alpha * (d * inv);
                t = (t >= 0.f) ? t : 0.2f * t;
                if (t > best) { second = best; best = t; bi = m; }
                else if (t > second) second = t;
            }
            flag = (best - second <= Tflag);
            if (!flag) {
                g_assign8[(size_t)bh * N_ + n] = (unsigned char)bi;
                g_sval[(size_t)bh * N_ + n]    = best;
            }
        }

        // warp-cooperative exact refinement of flagged tokens
        unsigned fl = __ballot_sync(0xffffffffu, valid && flag);
        while (fl) {
            int src = __ffs(fl) - 1;
            fl &= fl - 1;
            int nn = __shfl_sync(0xffffffffu, n, src);

            const float* xr = x + ((size_t)b * N_ + nn) * DIM_;
            float xr8[8];
#pragma unroll
            for (int j = 0; j < 8; j++) xr8[j] = xr[lane + j * 32];
            float fex[24];
#pragma unroll
            for (int k = 0; k < 24; k++) {
                const float* wr = f_w + (size_t)(e * 24 + k) * DIM_;
                float p = 0.f;
#pragma unroll
                for (int j = 0; j < 8; j++)
                    p = fmaf(xr8[j], wr[lane + j * 32], p);
#pragma unroll
                for (int off = 16; off > 0; off >>= 1)
                    p += __shfl_xor_sync(0xffffffffu, p, off);
                fex[k] = p + f_b[e * 24 + k];
            }
            float ss = 0.f;
#pragma unroll
            for (int k = 0; k < 24; k++) ss += fex[k] * fex[k];
            float inv = 1.f / fmaxf(sqrtf(ss), 1e-12f);

            float t = -FLT_MAX;
            int idx = 1000;
            if (lane < M_) {
                float d = 0.f;
#pragma unroll
                for (int k = 0; k < 24; k++) d = fmaf(cn[lane * HD_ + k], fex[k], d);
                t = beta + alpha * (d * inv);
                t = (t >= 0.f) ? t : 0.2f * t;
                idx = lane;
            }
#pragma unroll
            for (int off = 16; off > 0; off >>= 1) {
                float ot = __shfl_xor_sync(0xffffffffu, t, off);
                int   oi = __shfl_xor_sync(0xffffffffu, idx, off);
                if (ot > t || (ot == t && oi < idx)) { t = ot; idx = oi; }
            }
            if (lane == 0) {
                g_assign8[(size_t)bh * N_ + nn] = (unsigned char)idx;
                g_sval[(size_t)bh * N_ + nn]    = t;
            }
        }
    }
}

// =====================================================================
// K3b: aggregation. grid = BH_*16 (4096 blocks), 256 thr (8 warps).
// Warp w scans tokens [w*392, (w+1)*392) for center m; two-level reduce.
// =====================================================================
__global__ __launch_bounds__(256) void k_agg()
{
    __shared__ float part[8][28];   // 24 sums + count

    const int bh = blockIdx.x >> 4;
    const int m  = blockIdx.x & 15;
    const int tid = threadIdx.x;
    const int wid = tid >> 5, lane = tid & 31;

    float acc[24];
#pragma unroll
    for (int k = 0; k < 24; k++) acc[k] = 0.f;
    int cnt = 0;

    const unsigned char* asg = g_assign8 + (size_t)bh * N_;
    const int nb = wid * 392, ne = nb + 392;
    for (int n = nb + lane; n < ne; n += 32) {
        if (asg[n] == (unsigned char)m) {
            float s = g_sval[(size_t)bh * N_ + n];
            const float4* vp4 = (const float4*)(g_v + ((size_t)bh * N_ + n) * HD_);
#pragma unroll
            for (int q = 0; q < 6; q++) {
                float4 t = vp4[q];
                acc[q * 4 + 0] = fmaf(s, t.x, acc[q * 4 + 0]);
                acc[q * 4 + 1] = fmaf(s, t.y, acc[q * 4 + 1]);
                acc[q * 4 + 2] = fmaf(s, t.z, acc[q * 4 + 2]);
                acc[q * 4 + 3] = fmaf(s, t.w, acc[q * 4 + 3]);
            }
            cnt++;
        }
    }
#pragma unroll
    for (int off = 16; off > 0; off >>= 1) {
#pragma unroll
        for (int k = 0; k < 24; k++)
            acc[k] += __shfl_xor_sync(0xffffffffu, acc[k], off);
        cnt += __shfl_xor_sync(0xffffffffu, cnt, off);
    }
    if (lane == 0) {
#pragma unroll
        for (int k = 0; k < 24; k++) part[wid][k] = acc[k];
        part[wid][24] = (float)cnt;
    }
    __syncthreads();

    if (wid == 0 && lane < 25) {
        float s = 0.f;
#pragma unroll
        for (int w = 0; w < 8; w++) s += part[w][lane];
        part[0][lane] = s;
    }
    __syncthreads();

    if (tid < 24) {
        float denom = 1.f / (part[0][24] + 1.f);
        const float* vc = g_value_centers + (bh * M_ + m) * HD_;
        g_agg[(bh * M_ + m) * HD_ + tid] = (part[0][tid] + vc[tid]) * denom;
    }
}

// =====================================================================
// K4: dispatch + projection (round-7, assign8).
// =====================================================================
#define O_LDA 104   // 96 + 8
#define O_LDB 40    // 32 + 8
__global__ __launch_bounds__(128) void k_out_mma(
    const float* __restrict__ proj_b, float* __restrict__ out)
{
    __shared__ __align__(32) unsigned char pool[47104];
    __nv_bfloat16* Ah = (__nv_bfloat16*)pool;          // 64*104
    __nv_bfloat16* Al = Ah + 64 * O_LDA;
    __nv_bfloat16* Bh = Al + 64 * O_LDA;               // 128*40
    __nv_bfloat16* Bl = Bh + 128 * O_LDB;
    float* stage = (float*)pool;                       // 64 x 132

    const int tid = threadIdx.x;
    const int wid = tid >> 5;
    const int wm = wid & 1;
    const int wn = wid >> 1;
    const int r0 = blockIdx.x * 64;
    const int c0 = blockIdx.y * 128;
    const int bb = r0 / N_;
    const int n0 = r0 - bb * N_;

    for (int idx = tid; idx < 256; idx += 128) {
        int trow = idx >> 2, e = idx & 3;
        int n = n0 + trow;
        size_t aix = (size_t)(bb * HEADS_ + e) * N_ + n;
        int   c = g_assign8[aix];
        float s = g_sval[aix];
        const float* ag = g_agg + ((size_t)(bb * HEADS_ + e) * M_ + c) * HD_;
        uint32_t* ah = (uint32_t*)(Ah + trow * O_LDA + e * HD_);
        uint32_t* al = (uint32_t*)(Al + trow * O_LDA + e * HD_);
#pragma unroll
        for (int k2 = 0; k2 < 12; k2++) {
            __nv_bfloat16 h0, l0, h1, l1;
            bsplit(s * ag[2 * k2],     h0, l0);
            bsplit(s * ag[2 * k2 + 1], h1, l1);
            ah[k2] = packbf(h0, h1);
            al[k2] = packbf(l0, l1);
        }
    }

    FragC acc[2][4];
#pragma unroll
    for (int mi = 0; mi < 2; mi++)
#pragma unroll
        for (int ni = 0; ni < 4; ni++) wmma::fill_fragment(acc[mi][ni], 0.f);

    for (int ch = 0; ch < 3; ch++) {
        const int kc = ch * 32;
        __syncthreads();
#pragma unroll
        for (int s = tid; s < 512; s += 128) {
            int row = s >> 2, q = (s & 3) * 8;
            *(uint4*)(Bh + row * O_LDB + q) =
                *(const uint4*)(g_ph + (size_t)(c0 + row) * 96 + kc + q);
            *(uint4*)(Bl + row * O_LDB + q) =
                *(const uint4*)(g_pl + (size_t)(c0 + row) * 96 + kc + q);
        }
        __syncthreads();

#pragma unroll
        for (int ks = 0; ks < 32; ks += 16) {
            FragA ah2[2], al2[2];
#pragma unroll
            for (int mi = 0; mi < 2; mi++) {
                int rb = (wm * 32 + mi * 16) * O_LDA + kc + ks;
                wmma::load_matrix_sync(ah2[mi], Ah + rb, O_LDA);
                wmma::load_matrix_sync(al2[mi], Al + rb, O_LDA);
            }
#pragma unroll
            for (int ni = 0; ni < 4; ni++) {
                FragB bh, bl;
                int cb = (wn * 64 + ni * 16) * O_LDB + ks;
                wmma::load_matrix_sync(bh, Bh + cb, O_LDB);
                wmma::load_matrix_sync(bl, Bl + cb, O_LDB);
#pragma unroll
                for (int mi = 0; mi < 2; mi++) {
                    wmma::mma_sync(acc[mi][ni], ah2[mi], bh, acc[mi][ni]);
                    wmma::mma_sync(acc[mi][ni], ah2[mi], bl, acc[mi][ni]);
                    wmma::mma_sync(acc[mi][ni], al2[mi], bh, acc[mi][ni]);
                }
            }
        }
    }
    __syncthreads();

#pragma unroll
    for (int mi = 0; mi < 2; mi++)
#pragma unroll
        for (int ni = 0; ni < 4; ni++)
            wmma::store_matrix_sync(stage + (size_t)(wm * 32 + mi * 16) * 132
                                          + wn * 64 + ni * 16,
                                    acc[mi][ni], 132, wmma::mem_row_major);
    __syncthreads();

#pragma unroll
    for (int s = tid; s < 2048; s += 128) {
        int row = s >> 5, c4 = (s & 31) * 4;
        float4 v = *(float4*)(stage + row * 132 + c4);
        float4 b = *(const float4*)(proj_b + c0 + c4);
        v.x += b.x; v.y += b.y; v.z += b.z; v.w += b.w;
        *(float4*)(out + (size_t)(r0 + row) * OUT_ + c0 + c4) = v;
    }
}

// =====================================================================
extern "C" void kernel_launch(void* const* d_in, const int* in_sizes, int n_in,
                              void* d_out, int out_size)
{
    (void)in_sizes; (void)n_in; (void)out_size;
    const float* x         = (const float*)d_in[0];
    const float* f_w       = (const float*)d_in[1];
    const float* f_b       = (const float*)d_in[2];
    const float* v_w       = (const float*)d_in[3];
    const float* v_b       = (const float*)d_in[4];
    const float* proj_w    = (const float*)d_in[5];
    const float* proj_b    = (const float*)d_in[6];
    const float* sim_alpha = (const float*)d_in[7];
    const float* sim_beta  = (const float*)d_in[8];
    float* out = (float*)d_out;

    k_split_w<<<192, 256>>>(f_w, v_w, proj_w);
    k_gemm_fv_mma<<<(B_ * N_) / 64, 128>>>(x, f_b, v_b);
    k_centers<<<B_ * M_, 256>>>(x, f_w, f_b, v_w, v_b);
    k_assign<<<BH_ * 8, 256>>>(x, f_w, f_b, sim_alpha, sim_beta);
    k_agg<<<BH_ * M_, 256>>>();
    dim3 g2((B_ * N_) / 64, 2);
    k_out_mma<<<g2, 128>>>(proj_b, out);
}